// round 16
// baseline (speedup 1.0000x reference)
#include <cuda_runtime.h>
#include <cuda_bf16.h>
#include <cstdint>

// Problem constants (fixed by the dataset): B=512, T=512, L=128
#define BB 512
#define TT 512
#define LL 128
#define NB 8                  // batches per CTA = MMA N dimension
#define NCTA (BB / NB)        // 64 CTAs
#define PROWB 136             // padded bf16 P row (272 B): conflict-free B-frag LDS
#define C128 0.0078125f       // 2^-7 per-step rescale (ln128 == 7*ln2 exactly)
#define KFINAL 2474.5354346f  // 510 * 7 * ln2

// pack (lo, hi) floats -> bf16x2 register (lo = element 0 = even k)
static __device__ __forceinline__ uint32_t bf2(float lo, float hi) {
    uint32_t r;
    asm("cvt.rn.bf16x2.f32 %0, %1, %2;" : "=r"(r) : "f"(hi), "f"(lo));
    return r;
}
// m16n8k16 bf16 MMA, f32 accumulate in place (supported on base sm_103)
static __device__ __forceinline__ void hmma(float d[4], const uint32_t a[4],
                                            uint32_t b0, uint32_t b1) {
    asm volatile(
        "mma.sync.aligned.m16n8k16.row.col.f32.bf16.bf16.f32 "
        "{%0,%1,%2,%3}, {%4,%5,%6,%7}, {%8,%9}, {%0,%1,%2,%3};"
        : "+f"(d[0]), "+f"(d[1]), "+f"(d[2]), "+f"(d[3])
        : "r"(a[0]), "r"(a[1]), "r"(a[2]), "r"(a[3]), "r"(b0), "r"(b1));
}

// One CTA = 8 batches, 128 threads, 64 CTAs. Per step ONE 128x8x128 bf16
// matmul on the tensor pipe: warp w owns j in [32w, 32w+32) (2 m16 tiles),
// N = 8 batches, K = 128 as 8 k16 tiles. A = E^T lives in registers as MMA
// fragments (loaded once); B = P is bf16 in SMEM, double-buffered, padded to
// a 272-byte row so the B-fragment LDS.32 pattern (bank = 4*gid + tig) is
// conflict-free. Linear-domain recurrence with constant 2^-7 rescale (R9):
// D output IS next W; one __syncthreads per step; no log/exp on the path.
__global__ __launch_bounds__(128, 1) void crf_kernel(
    const float* __restrict__ feats,     // [B, T, L]
    const float* __restrict__ transfer,  // [L, L]
    const int*   __restrict__ target,    // [B, T]
    const int*   __restrict__ startp,
    const int*   __restrict__ stopp,
    float*       __restrict__ out)       // [B]
{
    __shared__ __align__(16) __nv_bfloat16 Pbuf[2][NB][PROWB];
    __shared__ float Sfin[NB][LL];
    __shared__ float smax[NB][4];
    __shared__ float ssum[NB][4];
    __shared__ float sg[NB][4];

    const int tid  = threadIdx.x;
    const int lane = tid & 31;
    const int w    = tid >> 5;
    const int gid  = lane >> 2;   // 0..7
    const int tig  = lane & 3;    // 0..3
    const int b0   = blockIdx.x * NB;

    const int start = startp ? *startp : (LL - 2);
    const int stop  = stopp  ? *stopp  : (LL - 1);

    // ---- A fragments: A[r][c] = exp(transfer[c][r]) (E^T), bf16, in regs ----
    // m16n8k16 A map: a0=(gid, 2tig), a1=(gid+8, 2tig), a2=(gid, 2tig+8), a3=(gid+8, 2tig+8)
    uint32_t Afr[2][8][4];
#pragma unroll
    for (int mt = 0; mt < 2; mt++)
#pragma unroll
        for (int kt = 0; kt < 8; kt++) {
            const int r0 = 32 * w + 16 * mt + gid;
            const int r1 = r0 + 8;
            const int c0 = kt * 16 + tig * 2;
            Afr[mt][kt][0] = bf2(__expf(transfer[c0 * LL + r0]),
                                 __expf(transfer[(c0 + 1) * LL + r0]));
            Afr[mt][kt][1] = bf2(__expf(transfer[c0 * LL + r1]),
                                 __expf(transfer[(c0 + 1) * LL + r1]));
            Afr[mt][kt][2] = bf2(__expf(transfer[(c0 + 8) * LL + r0]),
                                 __expf(transfer[(c0 + 9) * LL + r0]));
            Afr[mt][kt][3] = bf2(__expf(transfer[(c0 + 8) * LL + r1]),
                                 __expf(transfer[(c0 + 9) * LL + r1]));
        }

    // ---- This thread's 8 (j, b) output elements (D-fragment map) ----
    // d[mt][i]: j = 32w + 16mt + 8*(i>>1) + gid,  b = 2*tig + (i&1)
    int jp[8], bp[8];
    const float* fptr[8];
#pragma unroll
    for (int mt = 0; mt < 2; mt++)
#pragma unroll
        for (int i = 0; i < 4; i++) {
            const int p = mt * 4 + i;
            jp[p] = 32 * w + 16 * mt + 8 * (i >> 1) + gid;
            bp[p] = 2 * tig + (i & 1);
            fptr[p] = feats + (size_t)(b0 + bp[p]) * TT * LL + jp[p];
        }

    // ---- Gold-path partial sums (emit + trans) ----
    float g[NB];
#pragma unroll
    for (int nb = 0; nb < NB; nb++) {
        const float* fbn = feats  + (size_t)(b0 + nb) * TT * LL;
        const int*   tbn = target + (size_t)(b0 + nb) * TT;
        float acc = 0.f;
        for (int t = 1 + tid; t < TT; t += 128) {
            const int tg = tbn[t];
            const int pr = (t == 1) ? start : tbn[t - 1];
            acc += fbn[t * LL + tg] + transfer[pr * LL + tg];
        }
        g[nb] = acc;
    }

    // ---- Prologue: P(2) = exp(prev0 + f2) * 2^-7 (thread tid = column j) ----
    {
        const float tstart = transfer[start * LL + tid];
#pragma unroll
        for (int b = 0; b < NB; b++) {
            const float* f = feats + (size_t)(b0 + b) * TT * LL + tid;
            const float W2 = __expf(f[1 * LL] + tstart);
            Pbuf[0][b][tid] = __float2bfloat16(W2 * (__expf(f[2 * LL]) * C128));
        }
    }
    // efs pipelines for this thread's 8 (j,b) pairs: efs0 = exp(f(t+1))*2^-7
    float efs0[8], efs1[8], fraw[8];
#pragma unroll
    for (int p = 0; p < 8; p++) {
        efs0[p] = __expf(fptr[p][3 * LL]) * C128;
        efs1[p] = __expf(fptr[p][4 * LL]) * C128;
        fraw[p] = fptr[p][5 * LL];
    }
    __syncthreads();

    float Wp[8];

    // ---- Main scan: t = 2 .. TT-1 (510 tensor-core steps) ----
    for (int t = 2; t < TT; t++) {
        const int bufr = t & 1;        // t=2 reads buffer 0
        const int bufw = bufr ^ 1;

        // B fragments: b0 = P[gid][k16+2tig .. +1], b1 = +8 (conflict-free)
        uint32_t Bf0[8], Bf1[8];
#pragma unroll
        for (int kt = 0; kt < 8; kt++) {
            Bf0[kt] = *(const uint32_t*)&Pbuf[bufr][gid][kt * 16 + tig * 2];
            Bf1[kt] = *(const uint32_t*)&Pbuf[bufr][gid][kt * 16 + tig * 2 + 8];
        }

        // 4 independent accumulation chains (2 m-tiles x 2 k-halves), depth 4
        float accA[2][4] = {{0.f, 0.f, 0.f, 0.f}, {0.f, 0.f, 0.f, 0.f}};
        float accB[2][4] = {{0.f, 0.f, 0.f, 0.f}, {0.f, 0.f, 0.f, 0.f}};
#pragma unroll
        for (int kt = 0; kt < 4; kt++) {
            hmma(accA[0], Afr[0][kt],     Bf0[kt],     Bf1[kt]);
            hmma(accA[1], Afr[1][kt],     Bf0[kt],     Bf1[kt]);
            hmma(accB[0], Afr[0][kt + 4], Bf0[kt + 4], Bf1[kt + 4]);
            hmma(accB[1], Afr[1][kt + 4], Bf0[kt + 4], Bf1[kt + 4]);
        }

        const int tn = (t + 4 < TT) ? (t + 4) : (TT - 1);
#pragma unroll
        for (int mt = 0; mt < 2; mt++)
#pragma unroll
            for (int i = 0; i < 4; i++) {
                const int p = mt * 4 + i;
                const float W = accA[mt][i] + accB[mt][i];   // W(t+1)
                Wp[p] = W;
                Pbuf[bufw][bp[p]][jp[p]] =
                    __float2bfloat16(W * efs0[p]);           // P(t+1)
                efs0[p] = efs1[p];
                efs1[p] = __expf(fraw[p]) * C128;            // MUFU off-path
                fraw[p] = fptr[p][(size_t)tn * LL];
            }
        __syncthreads();
    }

    // ---- Scatter final W to SMEM, reconstruct prev per column ----
#pragma unroll
    for (int p = 0; p < 8; p++)
        Sfin[bp[p]][jp[p]] = Wp[p];
    __syncthreads();

    float prev[NB];
#pragma unroll
    for (int nb = 0; nb < NB; nb++)
        prev[nb] = __logf(Sfin[nb][tid]) + KFINAL;

    // ---- Epilogue: sentence scores and gold scores ----
    const float tstop = transfer[tid * LL + stop];
#pragma unroll
    for (int nb = 0; nb < NB; nb++) {
        float m = prev[nb] + tstop;
#pragma unroll
        for (int off = 16; off; off >>= 1)
            m = fmaxf(m, __shfl_xor_sync(0xffffffffu, m, off));
        if (lane == 0) smax[nb][w] = m;
    }
    __syncthreads();
#pragma unroll
    for (int nb = 0; nb < NB; nb++) {
        const float mm = fmaxf(fmaxf(smax[nb][0], smax[nb][1]),
                               fmaxf(smax[nb][2], smax[nb][3]));
        float es = __expf((prev[nb] + tstop) - mm);
        float gg = g[nb];
#pragma unroll
        for (int off = 16; off; off >>= 1) {
            es += __shfl_xor_sync(0xffffffffu, es, off);
            gg += __shfl_xor_sync(0xffffffffu, gg, off);
        }
        if (lane == 0) { ssum[nb][w] = es; sg[nb][w] = gg; }
    }
    __syncthreads();

    if (tid < NB) {
        const int nb = tid;
        const float mm = fmaxf(fmaxf(smax[nb][0], smax[nb][1]),
                               fmaxf(smax[nb][2], smax[nb][3]));
        const float Ssum = ssum[nb][0] + ssum[nb][1] + ssum[nb][2] + ssum[nb][3];
        const float sentence = mm + __logf(Ssum);
        const float gsum = sg[nb][0] + sg[nb][1] + sg[nb][2] + sg[nb][3];
        const float emit0 = feats[(size_t)(b0 + nb) * TT * LL + start];
        out[b0 + nb] = sentence - __expf(emit0 + gsum);
    }
}

extern "C" void kernel_launch(void* const* d_in, const int* in_sizes, int n_in,
                              void* d_out, int out_size) {
    const float* feats    = (const float*)d_in[0];
    const float* transfer = (const float*)d_in[1];
    const int*   target   = (const int*)d_in[2];
    const int*   startp   = (n_in >= 4) ? (const int*)d_in[3] : nullptr;
    const int*   stopp    = (n_in >= 5) ? (const int*)d_in[4] : nullptr;

    crf_kernel<<<NCTA, 128>>>(feats, transfer, target, startp, stopp,
                              (float*)d_out);
}

// round 17
// speedup vs baseline: 1.0105x; 1.0105x over previous
#include <cuda_runtime.h>
#include <cuda_bf16.h>
#include <cstdint>

// Problem constants (fixed by the dataset): B=512, T=512, L=128
#define BB 512
#define TT 512
#define LL 128
#define NB 8                  // batches per CTA = MMA N dimension
#define NCTA (BB / NB)        // 64 CTAs
#define PROWB 136             // padded bf16 P row (272 B): conflict-free B-frag LDS
#define C128 0.0078125f       // 2^-7 per-step rescale (ln128 == 7*ln2 exactly)
#define KFINAL 2474.5354346f  // 510 * 7 * ln2

// pack (lo, hi) floats -> bf16x2 register (lo = element 0 = even k)
static __device__ __forceinline__ uint32_t bf2(float lo, float hi) {
    uint32_t r;
    asm("cvt.rn.bf16x2.f32 %0, %1, %2;" : "=r"(r) : "f"(hi), "f"(lo));
    return r;
}
// m16n8k16 bf16 MMA, f32 accumulate in place (supported on base sm_103)
static __device__ __forceinline__ void hmma(float d[4], const uint32_t a[4],
                                            uint32_t b0, uint32_t b1) {
    asm volatile(
        "mma.sync.aligned.m16n8k16.row.col.f32.bf16.bf16.f32 "
        "{%0,%1,%2,%3}, {%4,%5,%6,%7}, {%8,%9}, {%0,%1,%2,%3};"
        : "+f"(d[0]), "+f"(d[1]), "+f"(d[2]), "+f"(d[3])
        : "r"(a[0]), "r"(a[1]), "r"(a[2]), "r"(a[3]), "r"(b0), "r"(b1));
}

// One CTA = 8 batches, 128 threads, 64 CTAs. Per step ONE 128x8x128 bf16
// matmul on the tensor pipe: warp w owns j in [32w, 32w+32) (2 m16 tiles),
// N = 8 batches, K = 128 as 8 k16 tiles. A = E^T lives in registers as MMA
// fragments (loaded once); B = P is bf16 in SMEM, double-buffered, padded to
// a 272-byte row so the B-fragment LDS.32 pattern (bank = 4*gid + tig) is
// conflict-free. Linear-domain recurrence with constant 2^-7 rescale (R9):
// D output IS next W; one __syncthreads per step; no log/exp on the path.
__global__ __launch_bounds__(128, 1) void crf_kernel(
    const float* __restrict__ feats,     // [B, T, L]
    const float* __restrict__ transfer,  // [L, L]
    const int*   __restrict__ target,    // [B, T]
    const int*   __restrict__ startp,
    const int*   __restrict__ stopp,
    float*       __restrict__ out)       // [B]
{
    __shared__ __align__(16) __nv_bfloat16 Pbuf[2][NB][PROWB];
    __shared__ float Sfin[NB][LL];
    __shared__ float smax[NB][4];
    __shared__ float ssum[NB][4];
    __shared__ float sg[NB][4];

    const int tid  = threadIdx.x;
    const int lane = tid & 31;
    const int w    = tid >> 5;
    const int gid  = lane >> 2;   // 0..7
    const int tig  = lane & 3;    // 0..3
    const int b0   = blockIdx.x * NB;

    const int start = startp ? *startp : (LL - 2);
    const int stop  = stopp  ? *stopp  : (LL - 1);

    // ---- A fragments: A[r][c] = exp(transfer[c][r]) (E^T), bf16, in regs ----
    // m16n8k16 A map: a0=(gid, 2tig), a1=(gid+8, 2tig), a2=(gid, 2tig+8), a3=(gid+8, 2tig+8)
    uint32_t Afr[2][8][4];
#pragma unroll
    for (int mt = 0; mt < 2; mt++)
#pragma unroll
        for (int kt = 0; kt < 8; kt++) {
            const int r0 = 32 * w + 16 * mt + gid;
            const int r1 = r0 + 8;
            const int c0 = kt * 16 + tig * 2;
            Afr[mt][kt][0] = bf2(__expf(transfer[c0 * LL + r0]),
                                 __expf(transfer[(c0 + 1) * LL + r0]));
            Afr[mt][kt][1] = bf2(__expf(transfer[c0 * LL + r1]),
                                 __expf(transfer[(c0 + 1) * LL + r1]));
            Afr[mt][kt][2] = bf2(__expf(transfer[(c0 + 8) * LL + r0]),
                                 __expf(transfer[(c0 + 9) * LL + r0]));
            Afr[mt][kt][3] = bf2(__expf(transfer[(c0 + 8) * LL + r1]),
                                 __expf(transfer[(c0 + 9) * LL + r1]));
        }

    // ---- This thread's 8 (j, b) output elements (D-fragment map) ----
    // d[mt][i]: j = 32w + 16mt + 8*(i>>1) + gid,  b = 2*tig + (i&1)
    int jp[8], bp[8];
    const float* fptr[8];
#pragma unroll
    for (int mt = 0; mt < 2; mt++)
#pragma unroll
        for (int i = 0; i < 4; i++) {
            const int p = mt * 4 + i;
            jp[p] = 32 * w + 16 * mt + 8 * (i >> 1) + gid;
            bp[p] = 2 * tig + (i & 1);
            fptr[p] = feats + (size_t)(b0 + bp[p]) * TT * LL + jp[p];
        }

    // ---- Gold-path partial sums (emit + trans) ----
    float g[NB];
#pragma unroll
    for (int nb = 0; nb < NB; nb++) {
        const float* fbn = feats  + (size_t)(b0 + nb) * TT * LL;
        const int*   tbn = target + (size_t)(b0 + nb) * TT;
        float acc = 0.f;
        for (int t = 1 + tid; t < TT; t += 128) {
            const int tg = tbn[t];
            const int pr = (t == 1) ? start : tbn[t - 1];
            acc += fbn[t * LL + tg] + transfer[pr * LL + tg];
        }
        g[nb] = acc;
    }

    // ---- Prologue: P(2) = exp(prev0 + f2) * 2^-7 (thread tid = column j) ----
    {
        const float tstart = transfer[start * LL + tid];
#pragma unroll
        for (int b = 0; b < NB; b++) {
            const float* f = feats + (size_t)(b0 + b) * TT * LL + tid;
            const float W2 = __expf(f[1 * LL] + tstart);
            Pbuf[0][b][tid] = __float2bfloat16(W2 * (__expf(f[2 * LL]) * C128));
        }
    }
    // efs pipelines for this thread's 8 (j,b) pairs: efs0 = exp(f(t+1))*2^-7
    float efs0[8], efs1[8], fraw[8];
#pragma unroll
    for (int p = 0; p < 8; p++) {
        efs0[p] = __expf(fptr[p][3 * LL]) * C128;
        efs1[p] = __expf(fptr[p][4 * LL]) * C128;
        fraw[p] = fptr[p][5 * LL];
    }
    __syncthreads();

    float Wp[8];

    // ---- Main scan: t = 2 .. TT-1 (510 tensor-core steps) ----
    for (int t = 2; t < TT; t++) {
        const int bufr = t & 1;        // t=2 reads buffer 0
        const int bufw = bufr ^ 1;

        // B fragments: b0 = P[gid][k16+2tig .. +1], b1 = +8 (conflict-free)
        uint32_t Bf0[8], Bf1[8];
#pragma unroll
        for (int kt = 0; kt < 8; kt++) {
            Bf0[kt] = *(const uint32_t*)&Pbuf[bufr][gid][kt * 16 + tig * 2];
            Bf1[kt] = *(const uint32_t*)&Pbuf[bufr][gid][kt * 16 + tig * 2 + 8];
        }

        // 4 independent accumulation chains (2 m-tiles x 2 k-halves), depth 4
        float accA[2][4] = {{0.f, 0.f, 0.f, 0.f}, {0.f, 0.f, 0.f, 0.f}};
        float accB[2][4] = {{0.f, 0.f, 0.f, 0.f}, {0.f, 0.f, 0.f, 0.f}};
#pragma unroll
        for (int kt = 0; kt < 4; kt++) {
            hmma(accA[0], Afr[0][kt],     Bf0[kt],     Bf1[kt]);
            hmma(accA[1], Afr[1][kt],     Bf0[kt],     Bf1[kt]);
            hmma(accB[0], Afr[0][kt + 4], Bf0[kt + 4], Bf1[kt + 4]);
            hmma(accB[1], Afr[1][kt + 4], Bf0[kt + 4], Bf1[kt + 4]);
        }

        const int tn = (t + 4 < TT) ? (t + 4) : (TT - 1);
#pragma unroll
        for (int mt = 0; mt < 2; mt++)
#pragma unroll
            for (int i = 0; i < 4; i++) {
                const int p = mt * 4 + i;
                const float W = accA[mt][i] + accB[mt][i];   // W(t+1)
                Wp[p] = W;
                Pbuf[bufw][bp[p]][jp[p]] =
                    __float2bfloat16(W * efs0[p]);           // P(t+1)
                efs0[p] = efs1[p];
                efs1[p] = __expf(fraw[p]) * C128;            // MUFU off-path
                fraw[p] = fptr[p][(size_t)tn * LL];
            }
        __syncthreads();
    }

    // ---- Scatter final W to SMEM, reconstruct prev per column ----
#pragma unroll
    for (int p = 0; p < 8; p++)
        Sfin[bp[p]][jp[p]] = Wp[p];
    __syncthreads();

    float prev[NB];
#pragma unroll
    for (int nb = 0; nb < NB; nb++)
        prev[nb] = __logf(Sfin[nb][tid]) + KFINAL;

    // ---- Epilogue: sentence scores and gold scores ----
    const float tstop = transfer[tid * LL + stop];
#pragma unroll
    for (int nb = 0; nb < NB; nb++) {
        float m = prev[nb] + tstop;
#pragma unroll
        for (int off = 16; off; off >>= 1)
            m = fmaxf(m, __shfl_xor_sync(0xffffffffu, m, off));
        if (lane == 0) smax[nb][w] = m;
    }
    __syncthreads();
#pragma unroll
    for (int nb = 0; nb < NB; nb++) {
        const float mm = fmaxf(fmaxf(smax[nb][0], smax[nb][1]),
                               fmaxf(smax[nb][2], smax[nb][3]));
        float es = __expf((prev[nb] + tstop) - mm);
        float gg = g[nb];
#pragma unroll
        for (int off = 16; off; off >>= 1) {
            es += __shfl_xor_sync(0xffffffffu, es, off);
            gg += __shfl_xor_sync(0xffffffffu, gg, off);
        }
        if (lane == 0) { ssum[nb][w] = es; sg[nb][w] = gg; }
    }
    __syncthreads();

    if (tid < NB) {
        const int nb = tid;
        const float mm = fmaxf(fmaxf(smax[nb][0], smax[nb][1]),
                               fmaxf(smax[nb][2], smax[nb][3]));
        const float Ssum = ssum[nb][0] + ssum[nb][1] + ssum[nb][2] + ssum[nb][3];
        const float sentence = mm + __logf(Ssum);
        const float gsum = sg[nb][0] + sg[nb][1] + sg[nb][2] + sg[nb][3];
        const float emit0 = feats[(size_t)(b0 + nb) * TT * LL + start];
        out[b0 + nb] = sentence - __expf(emit0 + gsum);
    }
}

extern "C" void kernel_launch(void* const* d_in, const int* in_sizes, int n_in,
                              void* d_out, int out_size) {
    const float* feats    = (const float*)d_in[0];
    const float* transfer = (const float*)d_in[1];
    const int*   target   = (const int*)d_in[2];
    const int*   startp   = (n_in >= 4) ? (const int*)d_in[3] : nullptr;
    const int*   stopp    = (n_in >= 5) ? (const int*)d_in[4] : nullptr;

    crf_kernel<<<NCTA, 128>>>(feats, transfer, target, startp, stopp,
                              (float*)d_out);
}